// round 6
// baseline (speedup 1.0000x reference)
#include <cuda_runtime.h>
#include <cstdint>

// ---------------- problem constants ----------------
#define B_SZ   32
#define CIN    128
#define H_IN   112
#define W_IN   112
#define COUT   256
#define OHW    55
#define STRIDE 2
#define M_TOT  (B_SZ * OHW * OHW)   // 96800
#define K_TOT  (CIN * 9)            // 1152
#define OPIX   (OHW * OHW)          // 3025
#define INHW   (H_IN * W_IN)        // 12544

// ---------------- GEMM tiling ----------------
#define BM 128
#define BN 128
#define BK 32
#define NT 128
#define KTILES (K_TOT / BK)         // 36

#define ASTRIDE 36
#define BSTRIDE 36
#define A_TILE_F (BM * ASTRIDE)     // 4608 floats
#define B_TILE_F (BN * BSTRIDE)     // 4608 floats
#define SMEM_BYTES (2 * (A_TILE_F + B_TILE_F) * 4)   // 73728

// k-permutation within each 8-group: pairs (k, k+4) become adjacent
__host__ __device__ __forceinline__ int kperm(int k) {
    return (k & ~7) | ((k & 3) << 1) | ((k >> 2) & 1);
}

// pre-converted, pre-permuted weights (tf32 bits as float)
__device__ float g_wperm[COUT * K_TOT];

__device__ __forceinline__ uint32_t smem_u32(const void* p) {
    uint32_t a;
    asm("{ .reg .u64 t; cvta.to.shared.u64 t, %1; cvt.u32.u64 %0, t; }" : "=r"(a) : "l"(p));
    return a;
}
__device__ __forceinline__ uint32_t to_tf32(float f) {
    uint32_t u;
    asm("cvt.rna.tf32.f32 %0, %1;" : "=r"(u) : "f"(f));
    return u;
}

#define CP_ASYNC4(dst, src, sz) \
    asm volatile("cp.async.ca.shared.global [%0], [%1], 4, %2;" \
                 :: "r"(dst), "l"(src), "r"(sz) : "memory")
#define CP_ASYNC16(dst, src) \
    asm volatile("cp.async.cg.shared.global [%0], [%1], 16;" \
                 :: "r"(dst), "l"(src) : "memory")
#define CP_COMMIT()  asm volatile("cp.async.commit_group;" ::: "memory")
#define CP_WAIT1()   asm volatile("cp.async.wait_group 1;"  ::: "memory")
#define CP_WAIT0()   asm volatile("cp.async.wait_group 0;"  ::: "memory")

__device__ __forceinline__ void mma_tf32(float& c0, float& c1, float& c2, float& c3,
                                         uint32_t a0, uint32_t a1, uint32_t a2, uint32_t a3,
                                         uint32_t b0, uint32_t b1) {
    asm volatile("mma.sync.aligned.m16n8k8.row.col.f32.tf32.tf32.f32 "
                 "{%0,%1,%2,%3}, {%4,%5,%6,%7}, {%8,%9}, {%0,%1,%2,%3};"
                 : "+f"(c0), "+f"(c1), "+f"(c2), "+f"(c3)
                 : "r"(a0), "r"(a1), "r"(a2), "r"(a3), "r"(b0), "r"(b1));
}

// ---------------- weight pre-convert/permute ----------------
__global__ void prep_weights_kernel(const float* __restrict__ w)
{
    const int idx = blockIdx.x * blockDim.x + threadIdx.x;
    if (idx < COUT * K_TOT) {
        const int n = idx / K_TOT;
        const int k = idx - n * K_TOT;
        g_wperm[n * K_TOT + kperm(k)] = __uint_as_float(to_tf32(w[idx]));
    }
}

// ---------------- main implicit-GEMM kernel ----------------
__global__ __launch_bounds__(NT, 2)
void conv_mma_tf32_kernel(const float* __restrict__ x,
                          float* __restrict__ out)
{
    extern __shared__ float sm[];
    const uint32_t sbase = smem_u32(sm);

    const int tid  = threadIdx.x;
    const int lane = tid & 31;
    const int wid  = tid >> 5;
    const int gid  = lane >> 2;     // 0..7
    const int qid  = lane & 3;      // 0..3
    const int warp_m = wid & 1;     // 0..1 -> m offset *64
    const int warp_n = wid >> 1;    // 0..1 -> n offset *64
    const int m0 = blockIdx.y * BM;
    const int n0 = blockIdx.x * BN;

    const int Aoff[2] = {0, A_TILE_F};
    const int Boff[2] = {2 * A_TILE_F, 2 * A_TILE_F + B_TILE_F};

    // ---- A gather: thread owns m-row = tid, all 32 k of the tile ----
    const int  mG     = m0 + tid;
    const bool mValid = (mG < M_TOT);
    const int  srcsz  = mValid ? 4 : 0;
    const int  mc  = mValid ? mG : (M_TOT - 1);
    const int  bA  = mc / OPIX;
    const int  rA  = mc - bA * OPIX;
    const int  ohA = rA / OHW;
    const int  owA = rA - ohA * OHW;
    const float* xrow = x + (size_t)bA * CIN * INHW
                          + (size_t)(ohA * STRIDE) * W_IN + owA * STRIDE;

    auto load_a = [&](int buf, int ktbase) {
        const uint32_t dst0 = sbase + (uint32_t)(Aoff[buf] + tid * ASTRIDE) * 4u;
        #pragma unroll
        for (int j = 0; j < BK; j++) {
            const int k   = ktbase + j;
            const int cin = k / 9;
            const int rs  = k - cin * 9;
            const int r   = rs / 3;
            const int s   = rs - r * 3;
            const float* g = xrow + (size_t)cin * INHW + r * W_IN + s;
            CP_ASYNC4(dst0 + 4u * kperm(j), g, srcsz);
        }
    };
    auto load_b = [&](int buf, int ktbase) {
        #pragma unroll
        for (int p = 0; p < 8; p++) {
            const int idx = tid + NT * p;
            const int row = idx >> 3;          // 0..127
            const int q   = idx & 7;           // float4 within 32 k
            const float* g = g_wperm + (size_t)(n0 + row) * K_TOT + ktbase + q * 4;
            const uint32_t dst = sbase + (uint32_t)(Boff[buf] + row * BSTRIDE + q * 4) * 4u;
            CP_ASYNC16(dst, g);
        }
    };

    float acc[4][8][4];
    #pragma unroll
    for (int i = 0; i < 4; i++)
        #pragma unroll
        for (int j = 0; j < 8; j++)
            #pragma unroll
            for (int e = 0; e < 4; e++)
                acc[i][j][e] = 0.0f;

    // ---- prologue: prime 2 stages ----
    load_a(0, 0);  load_b(0, 0);  CP_COMMIT();
    load_a(1, BK); load_b(1, BK); CP_COMMIT();

    for (int kt = 0; kt < KTILES; kt++) {
        const int buf = kt & 1;
        if (kt < KTILES - 2) CP_WAIT1(); else CP_WAIT0();
        __syncthreads();

        const float* A  = sm + Aoff[buf];
        const float* Bt = sm + Boff[buf];

        #pragma unroll
        for (int step = 0; step < 4; step++) {
            const int kc = step * 8 + qid * 2;    // permuted pair position
            uint32_t af[4][4];
            #pragma unroll
            for (int mt = 0; mt < 4; mt++) {
                const float2 p0 = *(const float2*)(A + (warp_m * 64 + mt * 16 + gid) * ASTRIDE + kc);
                const float2 p1 = *(const float2*)(A + (warp_m * 64 + mt * 16 + gid + 8) * ASTRIDE + kc);
                af[mt][0] = to_tf32(p0.x);
                af[mt][2] = to_tf32(p0.y);
                af[mt][1] = to_tf32(p1.x);
                af[mt][3] = to_tf32(p1.y);
            }
            uint32_t bf[8][2];
            #pragma unroll
            for (int nt = 0; nt < 8; nt++) {
                const float2 q = *(const float2*)(Bt + (warp_n * 64 + nt * 8 + gid) * BSTRIDE + kc);
                bf[nt][0] = __float_as_uint(q.x);   // pre-converted tf32
                bf[nt][1] = __float_as_uint(q.y);
            }
            #pragma unroll
            for (int mt = 0; mt < 4; mt++)
                #pragma unroll
                for (int nt = 0; nt < 8; nt++)
                    mma_tf32(acc[mt][nt][0], acc[mt][nt][1], acc[mt][nt][2], acc[mt][nt][3],
                             af[mt][0], af[mt][1], af[mt][2], af[mt][3],
                             bf[nt][0], bf[nt][1]);
        }
        __syncthreads();

        if (kt + 2 < KTILES) {
            load_a(buf, (kt + 2) * BK);
            load_b(buf, (kt + 2) * BK);
            CP_COMMIT();
        }
    }

    // ---- epilogue: direct register -> gmem scatter ----
    #pragma unroll
    for (int mt = 0; mt < 4; mt++) {
        const int mb = m0 + warp_m * 64 + mt * 16;
        #pragma unroll
        for (int half = 0; half < 2; half++) {
            const int m = mb + gid + half * 8;
            if (m < M_TOT) {
                const int b2  = m / OPIX;
                const int r2  = m - b2 * OPIX;
                const int oh2 = r2 / OHW;
                const int ow2 = r2 - oh2 * OHW;
                float* op = out + (size_t)b2 * COUT * OPIX + (size_t)oh2 * OHW + ow2;
                const int ncol0 = n0 + warp_n * 64 + qid * 2;
                #pragma unroll
                for (int nt = 0; nt < 8; nt++) {
                    const int n = ncol0 + nt * 8;
                    op[(size_t)n * OPIX]       = acc[mt][nt][half * 2 + 0];
                    op[(size_t)(n + 1) * OPIX] = acc[mt][nt][half * 2 + 1];
                }
            }
        }
    }
}

extern "C" void kernel_launch(void* const* d_in, const int* in_sizes, int n_in,
                              void* d_out, int out_size)
{
    const float* x = (const float*)d_in[0];
    const float* w = (const float*)d_in[1];
    float* out = (float*)d_out;

    cudaFuncSetAttribute(conv_mma_tf32_kernel,
                         cudaFuncAttributeMaxDynamicSharedMemorySize, SMEM_BYTES);

    prep_weights_kernel<<<(COUT * K_TOT + 255) / 256, 256>>>(w);

    dim3 grid(COUT / BN, (M_TOT + BM - 1) / BM);   // (2, 757)
    conv_mma_tf32_kernel<<<grid, NT, SMEM_BYTES>>>(x, out);
}

// round 7
// speedup vs baseline: 1.0797x; 1.0797x over previous
#include <cuda_runtime.h>
#include <cstdint>

// ---------------- problem constants ----------------
#define B_SZ   32
#define CIN    128
#define H_IN   112
#define W_IN   112
#define COUT   256
#define OHW    55
#define STRIDE 2
#define M_TOT  (B_SZ * OHW * OHW)   // 96800
#define K_TOT  (CIN * 9)            // 1152
#define OPIX   (OHW * OHW)          // 3025
#define INHW   (H_IN * W_IN)        // 12544

// ---------------- GEMM tiling ----------------
#define BM 128
#define BN 128
#define BK 32
#define NT 256
#define KTILES (K_TOT / BK)         // 36

#define ASTRIDE 36
#define BSTRIDE 36
#define A_TILE_F (BM * ASTRIDE)     // 4608 floats
#define B_TILE_F (BN * BSTRIDE)     // 4608 floats
#define SMEM_BYTES (2 * (A_TILE_F + B_TILE_F) * 4)   // 73728 -> 2 CTAs/SM

// k-permutation within each 8-group: pairs (k, k+4) become adjacent
__host__ __device__ __forceinline__ int kperm(int k) {
    return (k & ~7) | ((k & 3) << 1) | ((k >> 2) & 1);
}

// pre-converted (tf32), K-reordered (k' = rs*128 + cin), kperm'd weights
__device__ float g_wperm[COUT * K_TOT];

__device__ __forceinline__ uint32_t smem_u32(const void* p) {
    uint32_t a;
    asm("{ .reg .u64 t; cvta.to.shared.u64 t, %1; cvt.u32.u64 %0, t; }" : "=r"(a) : "l"(p));
    return a;
}
__device__ __forceinline__ uint32_t to_tf32(float f) {
    uint32_t u;
    asm("cvt.rna.tf32.f32 %0, %1;" : "=r"(u) : "f"(f));
    return u;
}

#define CP_ASYNC4(dst, src, sz) \
    asm volatile("cp.async.ca.shared.global [%0], [%1], 4, %2;" \
                 :: "r"(dst), "l"(src), "r"(sz) : "memory")
#define CP_ASYNC16(dst, src) \
    asm volatile("cp.async.cg.shared.global [%0], [%1], 16;" \
                 :: "r"(dst), "l"(src) : "memory")
#define CP_COMMIT()  asm volatile("cp.async.commit_group;" ::: "memory")
#define CP_WAIT1()   asm volatile("cp.async.wait_group 1;"  ::: "memory")
#define CP_WAIT0()   asm volatile("cp.async.wait_group 0;"  ::: "memory")

__device__ __forceinline__ void mma_tf32(float& c0, float& c1, float& c2, float& c3,
                                         uint32_t a0, uint32_t a1, uint32_t a2, uint32_t a3,
                                         uint32_t b0, uint32_t b1) {
    asm volatile("mma.sync.aligned.m16n8k8.row.col.f32.tf32.tf32.f32 "
                 "{%0,%1,%2,%3}, {%4,%5,%6,%7}, {%8,%9}, {%0,%1,%2,%3};"
                 : "+f"(c0), "+f"(c1), "+f"(c2), "+f"(c3)
                 : "r"(a0), "r"(a1), "r"(a2), "r"(a3), "r"(b0), "r"(b1));
}

// ---------------- weight pre-convert / K-reorder / permute ----------------
__global__ void prep_weights_kernel(const float* __restrict__ w)
{
    const int idx = blockIdx.x * blockDim.x + threadIdx.x;
    if (idx < COUT * K_TOT) {
        const int n   = idx / K_TOT;
        const int k   = idx - n * K_TOT;   // original: cin*9 + rs
        const int cin = k / 9;
        const int rs  = k - cin * 9;
        const int nk  = rs * CIN + cin;    // new K-order
        g_wperm[n * K_TOT + kperm(nk)] = __uint_as_float(to_tf32(w[idx]));
    }
}

// ---------------- main implicit-GEMM kernel ----------------
__global__ __launch_bounds__(NT, 2)
void conv_mma_tf32_kernel(const float* __restrict__ x,
                          float* __restrict__ out)
{
    extern __shared__ float sm[];
    const uint32_t sbase = smem_u32(sm);

    const int tid  = threadIdx.x;
    const int lane = tid & 31;
    const int wid  = tid >> 5;
    const int gid  = lane >> 2;     // 0..7
    const int qid  = lane & 3;      // 0..3
    const int warp_m = wid & 1;     // 0..1 -> m offset *64
    const int warp_n = wid >> 1;    // 0..3 -> n offset *32
    const int m0 = blockIdx.y * BM;
    const int n0 = blockIdx.x * BN;

    const int Aoff[2] = {0, A_TILE_F};
    const int Boff[2] = {2 * A_TILE_F, 2 * A_TILE_F + B_TILE_F};

    // ---- A gather: thread owns m-row = tid&127, 16 consecutive cin ----
    const int  mRow   = tid & 127;
    const int  kHalf  = (tid >> 7) * 16;
    const int  mG     = m0 + mRow;
    const bool mValid = (mG < M_TOT);
    const int  srcsz  = mValid ? 4 : 0;
    const int  mc  = mValid ? mG : (M_TOT - 1);
    const int  bA  = mc / OPIX;
    const int  rA  = mc - bA * OPIX;
    const int  ohA = rA / OHW;
    const int  owA = rA - ohA * OHW;
    const float* xrow = x + (size_t)bA * CIN * INHW
                          + (size_t)(ohA * STRIDE) * W_IN + owA * STRIDE;

    auto load_a = [&](int buf, int kt) {
        const int rs      = kt >> 2;           // 0..8, shared by whole tile
        const int cinbase = (kt & 3) * BK;
        const int r       = rs / 3;
        const int s       = rs - r * 3;
        const float* base = xrow + (size_t)(cinbase + kHalf) * INHW + r * W_IN + s;
        const uint32_t dst0 = sbase + (uint32_t)(Aoff[buf] + mRow * ASTRIDE) * 4u;
        #pragma unroll
        for (int j = 0; j < 16; j++)
            CP_ASYNC4(dst0 + 4u * (uint32_t)kperm(kHalf + j),
                      base + (size_t)j * INHW, srcsz);
    };
    auto load_b = [&](int buf, int kt) {
        #pragma unroll
        for (int p = 0; p < 4; p++) {
            const int idx = tid + NT * p;
            const int row = idx >> 3;          // 0..127
            const int q   = idx & 7;
            const float* g = g_wperm + (size_t)(n0 + row) * K_TOT + kt * BK + q * 4;
            const uint32_t dst = sbase + (uint32_t)(Boff[buf] + row * BSTRIDE + q * 4) * 4u;
            CP_ASYNC16(dst, g);
        }
    };

    float acc[4][4][4];
    #pragma unroll
    for (int i = 0; i < 4; i++)
        #pragma unroll
        for (int j = 0; j < 4; j++)
            #pragma unroll
            for (int e = 0; e < 4; e++)
                acc[i][j][e] = 0.0f;

    // ---- prologue: prime 2 stages ----
    load_a(0, 0); load_b(0, 0); CP_COMMIT();
    load_a(1, 1); load_b(1, 1); CP_COMMIT();

    for (int kt = 0; kt < KTILES; kt++) {
        const int buf = kt & 1;
        if (kt < KTILES - 2) CP_WAIT1(); else CP_WAIT0();
        __syncthreads();

        const float* A  = sm + Aoff[buf];
        const float* Bt = sm + Boff[buf];

        #pragma unroll
        for (int step = 0; step < 4; step++) {
            const int kc = step * 8 + qid * 2;    // permuted pair position
            uint32_t af[4][4];
            #pragma unroll
            for (int mt = 0; mt < 4; mt++) {
                const float2 p0 = *(const float2*)(A + (warp_m * 64 + mt * 16 + gid) * ASTRIDE + kc);
                const float2 p1 = *(const float2*)(A + (warp_m * 64 + mt * 16 + gid + 8) * ASTRIDE + kc);
                af[mt][0] = to_tf32(p0.x);
                af[mt][2] = to_tf32(p0.y);
                af[mt][1] = to_tf32(p1.x);
                af[mt][3] = to_tf32(p1.y);
            }
            uint32_t bf[4][2];
            #pragma unroll
            for (int nt = 0; nt < 4; nt++) {
                const float2 q = *(const float2*)(Bt + (warp_n * 32 + nt * 8 + gid) * BSTRIDE + kc);
                bf[nt][0] = __float_as_uint(q.x);   // pre-converted tf32
                bf[nt][1] = __float_as_uint(q.y);
            }
            #pragma unroll
            for (int mt = 0; mt < 4; mt++)
                #pragma unroll
                for (int nt = 0; nt < 4; nt++)
                    mma_tf32(acc[mt][nt][0], acc[mt][nt][1], acc[mt][nt][2], acc[mt][nt][3],
                             af[mt][0], af[mt][1], af[mt][2], af[mt][3],
                             bf[nt][0], bf[nt][1]);
        }
        __syncthreads();

        if (kt + 2 < KTILES) {
            load_a(buf, kt + 2);
            load_b(buf, kt + 2);
            CP_COMMIT();
        }
    }

    // ---- epilogue: direct register -> gmem scatter ----
    #pragma unroll
    for (int mt = 0; mt < 4; mt++) {
        const int mb = m0 + warp_m * 64 + mt * 16;
        #pragma unroll
        for (int half = 0; half < 2; half++) {
            const int m = mb + gid + half * 8;
            if (m < M_TOT) {
                const int b2  = m / OPIX;
                const int r2  = m - b2 * OPIX;
                const int oh2 = r2 / OHW;
                const int ow2 = r2 - oh2 * OHW;
                float* op = out + (size_t)b2 * COUT * OPIX + (size_t)oh2 * OHW + ow2;
                const int ncol0 = n0 + warp_n * 32 + qid * 2;
                #pragma unroll
                for (int nt = 0; nt < 4; nt++) {
                    const int n = ncol0 + nt * 8;
                    op[(size_t)n * OPIX]       = acc[mt][nt][half * 2 + 0];
                    op[(size_t)(n + 1) * OPIX] = acc[mt][nt][half * 2 + 1];
                }
            }
        }
    }
}

extern "C" void kernel_launch(void* const* d_in, const int* in_sizes, int n_in,
                              void* d_out, int out_size)
{
    const float* x = (const float*)d_in[0];
    const float* w = (const float*)d_in[1];
    float* out = (float*)d_out;

    cudaFuncSetAttribute(conv_mma_tf32_kernel,
                         cudaFuncAttributeMaxDynamicSharedMemorySize, SMEM_BYTES);

    prep_weights_kernel<<<(COUT * K_TOT + 255) / 256, 256>>>(w);

    dim3 grid(COUT / BN, (M_TOT + BM - 1) / BM);   // (2, 757)
    conv_mma_tf32_kernel<<<grid, NT, SMEM_BYTES>>>(x, out);
}

// round 8
// speedup vs baseline: 1.3268x; 1.2289x over previous
#include <cuda_runtime.h>
#include <cstdint>

// ---------------- problem constants ----------------
#define B_SZ   32
#define CIN    128
#define H_IN   112
#define W_IN   112
#define COUT   256
#define OHW    55
#define STRIDE 2
#define M_TOT  (B_SZ * OHW * OHW)   // 96800
#define K_TOT  (CIN * 9)            // 1152
#define OPIX   (OHW * OHW)          // 3025
#define INHW   (H_IN * W_IN)        // 12544

// ---------------- GEMM tiling ----------------
#define BM 128
#define BN 256
#define BK 32
#define NT 256
#define KTILES (K_TOT / BK)         // 36
#define NSTAGE 3

#define ASTRIDE 36
#define BSTRIDE 36
#define A_TILE_F (BM * ASTRIDE)     // 4608 floats
#define B_TILE_F (BN * BSTRIDE)     // 9216 floats
#define STAGE_F  (A_TILE_F + B_TILE_F)
#define SMEM_BYTES (NSTAGE * STAGE_F * 4)   // 165888

// permutation of 32-k group: thread qid's 8 values (4 steps x 2 halves) contiguous
// k = step*8 + half*4 + qid  ->  pos = qid*8 + step*2 + half
__host__ __device__ __forceinline__ int kperm(int k) {
    return (k & 3) * 8 + ((k >> 3) << 1) + ((k >> 2) & 1);
}

// pre-converted (tf32), K-reordered (k' = rs*128 + cin), kperm'd weights
__device__ float g_wperm[COUT * K_TOT];

__device__ __forceinline__ uint32_t smem_u32(const void* p) {
    uint32_t a;
    asm("{ .reg .u64 t; cvta.to.shared.u64 t, %1; cvt.u32.u64 %0, t; }" : "=r"(a) : "l"(p));
    return a;
}
__device__ __forceinline__ uint32_t to_tf32(float f) {
    uint32_t u;
    asm("cvt.rna.tf32.f32 %0, %1;" : "=r"(u) : "f"(f));
    return u;
}

#define CP_ASYNC4(dst, src, sz) \
    asm volatile("cp.async.ca.shared.global [%0], [%1], 4, %2;" \
                 :: "r"(dst), "l"(src), "r"(sz) : "memory")
#define CP_ASYNC16(dst, src) \
    asm volatile("cp.async.cg.shared.global [%0], [%1], 16;" \
                 :: "r"(dst), "l"(src) : "memory")
#define CP_COMMIT()  asm volatile("cp.async.commit_group;" ::: "memory")
#define CP_WAIT2()   asm volatile("cp.async.wait_group 2;"  ::: "memory")
#define CP_WAIT1()   asm volatile("cp.async.wait_group 1;"  ::: "memory")
#define CP_WAIT0()   asm volatile("cp.async.wait_group 0;"  ::: "memory")

__device__ __forceinline__ void mma_tf32(float& c0, float& c1, float& c2, float& c3,
                                         uint32_t a0, uint32_t a1, uint32_t a2, uint32_t a3,
                                         uint32_t b0, uint32_t b1) {
    asm volatile("mma.sync.aligned.m16n8k8.row.col.f32.tf32.tf32.f32 "
                 "{%0,%1,%2,%3}, {%4,%5,%6,%7}, {%8,%9}, {%0,%1,%2,%3};"
                 : "+f"(c0), "+f"(c1), "+f"(c2), "+f"(c3)
                 : "r"(a0), "r"(a1), "r"(a2), "r"(a3), "r"(b0), "r"(b1));
}

// ---------------- weight pre-convert / K-reorder / permute ----------------
__global__ void prep_weights_kernel(const float* __restrict__ w)
{
    const int idx = blockIdx.x * blockDim.x + threadIdx.x;
    if (idx < COUT * K_TOT) {
        const int n   = idx / K_TOT;
        const int k   = idx - n * K_TOT;   // original: cin*9 + rs
        const int cin = k / 9;
        const int rs  = k - cin * 9;
        const int nk  = rs * CIN + cin;    // new K-order
        g_wperm[n * K_TOT + (nk & ~31) + kperm(nk & 31)] =
            __uint_as_float(to_tf32(w[idx]));
    }
}

// ---------------- main implicit-GEMM kernel ----------------
__global__ __launch_bounds__(NT, 1)
void conv_mma_tf32_kernel(const float* __restrict__ x,
                          float* __restrict__ out)
{
    extern __shared__ float sm[];
    const uint32_t sbase = smem_u32(sm);

    const int tid  = threadIdx.x;
    const int lane = tid & 31;
    const int wid  = tid >> 5;
    const int gid  = lane >> 2;     // 0..7
    const int qid  = lane & 3;      // 0..3
    const int warp_m = wid & 1;     // 0..1 -> m offset *64
    const int warp_n = wid >> 1;    // 0..3 -> n offset *64
    const int m0 = blockIdx.x * BM;

    // ---- A gather: thread owns m-row = tid&127, 16 consecutive cin ----
    const int  mRow   = tid & 127;
    const int  kH8    = (tid >> 7) * 2;    // 16-k half -> step offset (0 or 2)
    const int  kHalf  = (tid >> 7) * 16;
    const int  mG     = m0 + mRow;
    const bool mValid = (mG < M_TOT);
    const int  srcsz  = mValid ? 4 : 0;
    const int  mc  = mValid ? mG : (M_TOT - 1);
    const int  bA  = mc / OPIX;
    const int  rA  = mc - bA * OPIX;
    const int  ohA = rA / OHW;
    const int  owA = rA - ohA * OHW;
    const float* xrow = x + (size_t)bA * CIN * INHW
                          + (size_t)(ohA * STRIDE) * W_IN + owA * STRIDE;

    auto load_a = [&](int buf, int kt) {
        const int rs      = kt >> 2;           // 0..8, shared by whole tile
        const int cinbase = (kt & 3) * BK;
        const int r       = rs / 3;
        const int s       = rs - r * 3;
        const float* base = xrow + (size_t)(cinbase + kHalf) * INHW + r * W_IN + s;
        const uint32_t dst0 = sbase + (uint32_t)(buf * STAGE_F + mRow * ASTRIDE + kH8 * 2) * 4u;
        #pragma unroll
        for (int j = 0; j < 16; j++) {
            // local k = kHalf + j; pos = kperm(j) + kH8*2 (kperm(j) compile-time)
            const int posj = (j & 3) * 8 + ((j >> 3) << 1) + ((j >> 2) & 1);
            CP_ASYNC4(dst0 + 4u * (uint32_t)posj, base + (size_t)j * INHW, srcsz);
        }
    };
    auto load_b = [&](int buf, int kt) {
        #pragma unroll
        for (int p = 0; p < 8; p++) {
            const int idx = tid + NT * p;
            const int row = idx >> 3;          // 0..255
            const int q   = idx & 7;
            const float* g = g_wperm + (size_t)row * K_TOT + kt * BK + q * 4;
            const uint32_t dst = sbase +
                (uint32_t)(buf * STAGE_F + A_TILE_F + row * BSTRIDE + q * 4) * 4u;
            CP_ASYNC16(dst, g);
        }
    };

    float acc[4][8][4];
    #pragma unroll
    for (int i = 0; i < 4; i++)
        #pragma unroll
        for (int j = 0; j < 8; j++)
            #pragma unroll
            for (int e = 0; e < 4; e++)
                acc[i][j][e] = 0.0f;

    // ---- prologue: prime 3 stages ----
    load_a(0, 0); load_b(0, 0); CP_COMMIT();
    load_a(1, 1); load_b(1, 1); CP_COMMIT();
    load_a(2, 2); load_b(2, 2); CP_COMMIT();

    int buf = 0;
    for (int kt = 0; kt < KTILES; kt++) {
        if (kt <= KTILES - 3)      CP_WAIT2();
        else if (kt == KTILES - 2) CP_WAIT1();
        else                       CP_WAIT0();
        __syncthreads();

        const float* A  = sm + buf * STAGE_F;
        const float* Bt = A + A_TILE_F;

        #pragma unroll
        for (int sp = 0; sp < 2; sp++) {          // step pairs
            float4 av[4][2];
            #pragma unroll
            for (int mt = 0; mt < 4; mt++) {
                av[mt][0] = *(const float4*)(A + (warp_m * 64 + mt * 16 + gid) * ASTRIDE + qid * 8 + sp * 4);
                av[mt][1] = *(const float4*)(A + (warp_m * 64 + mt * 16 + gid + 8) * ASTRIDE + qid * 8 + sp * 4);
            }
            float4 bv[8];
            #pragma unroll
            for (int nt = 0; nt < 8; nt++)
                bv[nt] = *(const float4*)(Bt + (warp_n * 64 + nt * 8 + gid) * BSTRIDE + qid * 8 + sp * 4);

            // step h=0 within pair: components .x (half0), .y (half1)
            #pragma unroll
            for (int mt = 0; mt < 4; mt++) {
                const uint32_t a0 = to_tf32(av[mt][0].x);
                const uint32_t a1 = to_tf32(av[mt][1].x);
                const uint32_t a2 = to_tf32(av[mt][0].y);
                const uint32_t a3 = to_tf32(av[mt][1].y);
                #pragma unroll
                for (int nt = 0; nt < 8; nt++)
                    mma_tf32(acc[mt][nt][0], acc[mt][nt][1], acc[mt][nt][2], acc[mt][nt][3],
                             a0, a1, a2, a3,
                             __float_as_uint(bv[nt].x), __float_as_uint(bv[nt].y));
            }
            // step h=1 within pair: components .z, .w
            #pragma unroll
            for (int mt = 0; mt < 4; mt++) {
                const uint32_t a0 = to_tf32(av[mt][0].z);
                const uint32_t a1 = to_tf32(av[mt][1].z);
                const uint32_t a2 = to_tf32(av[mt][0].w);
                const uint32_t a3 = to_tf32(av[mt][1].w);
                #pragma unroll
                for (int nt = 0; nt < 8; nt++)
                    mma_tf32(acc[mt][nt][0], acc[mt][nt][1], acc[mt][nt][2], acc[mt][nt][3],
                             a0, a1, a2, a3,
                             __float_as_uint(bv[nt].z), __float_as_uint(bv[nt].w));
            }
        }
        __syncthreads();

        if (kt + 3 < KTILES) {
            load_a(buf, kt + 3);
            load_b(buf, kt + 3);
            CP_COMMIT();
        }
        buf = (buf == NSTAGE - 1) ? 0 : buf + 1;
    }

    // ---- epilogue: direct register -> gmem scatter ----
    #pragma unroll
    for (int mt = 0; mt < 4; mt++) {
        const int mb = m0 + warp_m * 64 + mt * 16;
        #pragma unroll
        for (int half = 0; half < 2; half++) {
            const int m = mb + gid + half * 8;
            if (m < M_TOT) {
                const int b2  = m / OPIX;
                const int r2  = m - b2 * OPIX;
                const int oh2 = r2 / OHW;
                const int ow2 = r2 - oh2 * OHW;
                float* op = out + (size_t)b2 * COUT * OPIX + (size_t)oh2 * OHW + ow2;
                const int ncol0 = warp_n * 64 + qid * 2;
                #pragma unroll
                for (int nt = 0; nt < 8; nt++) {
                    const int n = ncol0 + nt * 8;
                    op[(size_t)n * OPIX]       = acc[mt][nt][half * 2 + 0];
                    op[(size_t)(n + 1) * OPIX] = acc[mt][nt][half * 2 + 1];
                }
            }
        }
    }
}

extern "C" void kernel_launch(void* const* d_in, const int* in_sizes, int n_in,
                              void* d_out, int out_size)
{
    const float* x = (const float*)d_in[0];
    const float* w = (const float*)d_in[1];
    float* out = (float*)d_out;

    cudaFuncSetAttribute(conv_mma_tf32_kernel,
                         cudaFuncAttributeMaxDynamicSharedMemorySize, SMEM_BYTES);

    prep_weights_kernel<<<(COUT * K_TOT + 255) / 256, 256>>>(w);

    const int grid = (M_TOT + BM - 1) / BM;   // 757
    conv_mma_tf32_kernel<<<grid, NT, SMEM_BYTES>>>(x, out);
}